// round 1
// baseline (speedup 1.0000x reference)
#include <cuda_runtime.h>
#include <math.h>

#define NN    4096
#define NI_   1024
#define NB    8
#define NT    500
#define NCTA  128
#define TPB   256
#define NWORD 128   // NN/32

// ---- device scratch (static: no allocations allowed) ----
__device__ float     g_weff[(size_t)NN * NN];          // 64 MB: weights * pairwise scaling
__device__ float     g_dff[(size_t)NT * NB * NN];      // 65.5 MB: precomputed FF drive [t][b*N+j]
__device__ unsigned  g_mask[2][2][NB][NWORD];          // [buf][type][batch][word] spike bitmasks
__device__ unsigned  g_count;                          // monotonic grid-barrier counter

struct SimConsts {
    float ar[4], ad[4], omad[4], esyn[4];
    float dtt0, dtt1;   // DT/tau_mem per cell type
};

// ------------------------------------------------------------------
// init: zero barrier counter and spike-mask buffer 0 (initial s = 0)
// ------------------------------------------------------------------
__global__ void init_kernel() {
    int idx = blockIdx.x * blockDim.x + threadIdx.x;
    if (idx == 0) g_count = 0u;
    if (idx < 2 * NB * NWORD) ((unsigned*)g_mask[0])[idx] = 0u;
}

// ------------------------------------------------------------------
// W_eff[i,j] = round( weights[i,j] * scal[ci[i], ci[j]] )   (matches
// the reference's elementwise scaling rounding exactly)
// ------------------------------------------------------------------
__global__ void weff_kernel(const float* __restrict__ W,
                            const float* __restrict__ scal,
                            const int*   __restrict__ ci) {
    int idx = blockIdx.x * TPB + threadIdx.x;
    int i = idx >> 12;
    int j = idx & (NN - 1);
    float f = __ldg(&scal[__ldg(&ci[i]) * 2 + __ldg(&ci[j])]);
    g_weff[idx] = __fmul_rn(__ldg(&W[idx]), f);
}

// ------------------------------------------------------------------
// FF drive: dff[t,b,j] = sum_i spikes[b,t,i] * round(Wff[i,j]*sFF[cf_i,ct_j])
// ascending i, matching the reference einsum summation order.
// One CTA per (t,b); 256 threads x 16 columns each.
// ------------------------------------------------------------------
__global__ void ff_kernel(const float* __restrict__ sp,
                          const float* __restrict__ wff,
                          const float* __restrict__ sff,
                          const int*   __restrict__ ciff,
                          const int*   __restrict__ ci) {
    __shared__ float s_sp[NI_];
    __shared__ float s_fe[NI_];
    __shared__ float s_fi[NI_];

    const int x   = blockIdx.x;        // t*NB + b
    const int t   = x >> 3;
    const int b   = x & 7;
    const int tid = threadIdx.x;

    for (int i = tid; i < NI_; i += TPB) {
        s_sp[i] = sp[((size_t)b * NT + t) * NI_ + i];
        int cf = __ldg(&ciff[i]) * 2;
        s_fe[i] = __ldg(&sff[cf]);
        s_fi[i] = __ldg(&sff[cf + 1]);
    }
    int ct[16];
#pragma unroll
    for (int jj = 0; jj < 16; jj++) ct[jj] = __ldg(&ci[jj * TPB + tid]);
    __syncthreads();

    float acc[16];
#pragma unroll
    for (int jj = 0; jj < 16; jj++) acc[jj] = 0.0f;

    for (int i = 0; i < NI_; ++i) {
        if (s_sp[i] != 0.0f) {                     // uniform across block
            float fe = s_fe[i], fi = s_fi[i];
            const float* wr = wff + (size_t)i * NN + tid;
#pragma unroll
            for (int jj = 0; jj < 16; jj++) {
                float f = ct[jj] ? fi : fe;
                acc[jj] = __fadd_rn(acc[jj], __fmul_rn(__ldg(wr + jj * TPB), f));
            }
        }
    }
    size_t o = (size_t)x * NN + tid;               // [t][b][j]
#pragma unroll
    for (int jj = 0; jj < 16; jj++) g_dff[o + jj * TPB] = acc[jj];
}

// ------------------------------------------------------------------
// Persistent simulation kernel: 128 CTAs x 256 threads = 1 thread per
// (batch, neuron). Grid barrier per step; spikes exchanged via bitmasks.
// ------------------------------------------------------------------
__global__ void __launch_bounds__(TPB, 1)
sim_kernel(const int* __restrict__ ci, float* __restrict__ out, SimConsts C) {
    __shared__ int s_lst[NN];     // compacted spike indices (pre-shifted <<12)
    __shared__ int s_wsum[8];
    __shared__ int s_woff[9];

    const int tid  = threadIdx.x;
    const int g    = blockIdx.x * TPB + tid;
    const int b    = g >> 12;
    const int j    = g & (NN - 1);
    const int lane = tid & 31;
    const int wrp  = tid >> 5;
    const int myct = __ldg(&ci[j]);

    const float dtt      = myct ? C.dtt1 : C.dtt0;
    const float refsteps = myct ? 10.0f : 20.0f;
    const float theta = -50.0f, u_reset = -65.0f, e_l = -70.0f, g_l = 10.0f;

    float v = e_l, ref = 0.0f;
    float h0 = 0, h1 = 0, h2 = 0, h3 = 0;
    float q0 = 0, q1 = 0, q2 = 0, q3 = 0;

    const float* __restrict__ Wcol = g_weff + j;
    float* outp = out + ((size_t)b * NT) * NN + j;

    for (int t = 0; t < NT; ++t) {
        const int p = t & 1;

        // ---- load spike masks, build ascending compact lists ----
        unsigned mword = (tid < NWORD) ? __ldcg(&g_mask[p][0][b][tid])
                                       : __ldcg(&g_mask[p][1][b][tid - NWORD]);
        int c = __popc(mword);
        int incl = c;
#pragma unroll
        for (int d = 1; d < 32; d <<= 1) {
            int nb2 = __shfl_up_sync(0xffffffffu, incl, d);
            if (lane >= d) incl += nb2;
        }
        if (lane == 31) s_wsum[wrp] = incl;
        __syncthreads();
        if (tid == 0) {
            int run = 0;
#pragma unroll
            for (int k = 0; k < 8; ++k) { s_woff[k] = run; run += s_wsum[k]; }
            s_woff[8] = run;
        }
        __syncthreads();
        int base = s_woff[wrp] + incl - c;
        const int totE = s_woff[4];
        const int totA = s_woff[8];
        {
            unsigned m = mword;
            int ib = ((tid < NWORD) ? tid : (tid - NWORD)) << 5;
            while (m) {
                int bit = __ffs(m) - 1;
                m &= m - 1;
                s_lst[base++] = (ib + bit) << 12;   // i*NN (element offset)
            }
        }
        __syncthreads();

        // ---- recurrent drive: strict sequential adds (ascending i) ----
        float acc_e = 0.0f, acc_i = 0.0f;
#pragma unroll 4
        for (int k = 0; k < totE; ++k)
            acc_e = __fadd_rn(acc_e, __ldg(Wcol + s_lst[k]));
#pragma unroll 4
        for (int k = totE; k < totA; ++k)
            acc_i = __fadd_rn(acc_i, __ldg(Wcol + s_lst[k]));

        float dff = __ldg(&g_dff[(size_t)t * (NB * NN) + g]);

        // ---- conductance kinetics + membrane update ----
        h0 = __fmaf_rn(h0, C.ar[0], acc_e);
        h1 = __fmaf_rn(h1, C.ar[1], __fmul_rn(acc_e, 0.5f));
        h2 = __fmaf_rn(h2, C.ar[2], acc_i);
        h3 = __fmaf_rn(h3, C.ar[3], dff);
        q0 = __fmaf_rn(q0, C.ad[0], __fmul_rn(C.omad[0], h0));
        q1 = __fmaf_rn(q1, C.ad[1], __fmul_rn(C.omad[1], h1));
        q2 = __fmaf_rn(q2, C.ad[2], __fmul_rn(C.omad[2], h2));
        q3 = __fmaf_rn(q3, C.ad[3], __fmul_rn(C.omad[3], h3));

        float I = __fmul_rn(q0, __fsub_rn(C.esyn[0], v));
        I = __fadd_rn(I, __fmul_rn(q1, __fsub_rn(C.esyn[1], v)));
        I = __fadd_rn(I, __fmul_rn(q2, __fsub_rn(C.esyn[2], v)));
        I = __fadd_rn(I, __fmul_rn(q3, __fsub_rn(C.esyn[3], v)));

        float vn = __fmaf_rn(dtt,
                             __fadd_rn(__fsub_rn(e_l, v), __fdiv_rn(I, g_l)),
                             v);
        bool refr = (ref > 0.0f);
        if (refr) vn = u_reset;
        bool  spk = (!refr) && (vn > theta);
        float sn  = spk ? 1.0f : 0.0f;
        v   = spk ? u_reset : vn;
        ref = spk ? refsteps : fmaxf(__fsub_rn(ref, 1.0f), 0.0f);
        outp[(size_t)t * NN] = sn;

        // ---- publish spike bitmasks for step t+1 ----
        unsigned be = __ballot_sync(0xffffffffu, spk && (myct == 0));
        unsigned bi = __ballot_sync(0xffffffffu, spk && (myct == 1));
        if (lane == 0) {
            const int qb   = p ^ 1;
            const int word = j >> 5;              // 0..127 within batch
            g_mask[qb][0][b][word] = be;
            g_mask[qb][1][b][word] = bi;
        }

        // ---- grid-wide barrier (monotonic counter) ----
        if (t != NT - 1) {
            __threadfence();
            __syncthreads();
            if (tid == 0) {
                atomicAdd(&g_count, 1u);
                const unsigned target = (unsigned)NCTA * (unsigned)(t + 1);
                while (*(volatile unsigned*)&g_count < target) { }
            }
            __syncthreads();
        }
    }
}

// ------------------------------------------------------------------
extern "C" void kernel_launch(void* const* d_in, const int* in_sizes, int n_in,
                              void* d_out, int out_size) {
    const float* in_spikes = (const float*)d_in[0];  // (B,T,NI)
    const float* weights   = (const float*)d_in[1];  // (N,N)
    const float* wff       = (const float*)d_in[2];  // (NI,N)
    const float* scal      = (const float*)d_in[3];  // (2,2)
    const float* scalff    = (const float*)d_in[4];  // (1,2)
    const int*   ci        = (const int*)  d_in[5];  // (N,)
    const int*   ciff      = (const int*)  d_in[6];  // (NI,)
    float*       out       = (float*)d_out;          // (B,T,N)

    // constants computed exactly as jnp.float32 would: f32 quotient, then
    // correctly-rounded exp (double -> float)
    const float tau_rise[4]  = {0.5f, 2.0f, 0.5f, 0.5f};
    const float tau_decay[4] = {2.0f, 100.0f, 5.0f, 2.0f};
    SimConsts C;
    for (int s = 0; s < 4; ++s) {
        float qr = -(0.1f / tau_rise[s]);
        float qd = -(0.1f / tau_decay[s]);
        C.ar[s]   = (float)exp((double)qr);
        C.ad[s]   = (float)exp((double)qd);
        C.omad[s] = 1.0f - C.ad[s];
    }
    C.esyn[0] = 0.0f; C.esyn[1] = 0.0f; C.esyn[2] = -80.0f; C.esyn[3] = 0.0f;
    C.dtt0 = 0.1f / 20.0f;
    C.dtt1 = 0.1f / 10.0f;

    init_kernel<<<8, TPB>>>();
    weff_kernel<<<(NN * NN) / TPB, TPB>>>(weights, scal, ci);
    ff_kernel<<<NT * NB, TPB>>>(in_spikes, wff, scalff, ciff, ci);
    sim_kernel<<<NCTA, TPB>>>(ci, out, C);
}

// round 2
// speedup vs baseline: 1.0945x; 1.0945x over previous
#include <cuda_runtime.h>
#include <math.h>

#define NN    4096
#define NI_   1024
#define NB    8
#define NT    500
#define TPB   256
#define NCTA  256    // 32 CTAs per batch, 128 columns each
#define NWORD 128    // NN/32

// ---- device scratch (static: no allocations allowed) ----
__device__ float     g_weff[(size_t)NN * NN];          // 64 MB
__device__ float     g_dff[(size_t)NT * NB * NN];      // 65.5 MB  [t][b*N+j]
__device__ unsigned  g_mask[2][2][NB][NWORD];          // [buf][type][batch][word]
__device__ unsigned  g_count;

struct SimConsts {
    float ar[4], ad[4], omad[4], esyn[4];
    float dtt0, dtt1;
};

// ------------------------------------------------------------------
__global__ void init_kernel() {
    int idx = blockIdx.x * blockDim.x + threadIdx.x;
    if (idx == 0) g_count = 0u;
    if (idx < 2 * NB * NWORD) ((unsigned*)g_mask[0])[idx] = 0u;
}

// ------------------------------------------------------------------
__global__ void weff_kernel(const float* __restrict__ W,
                            const float* __restrict__ scal,
                            const int*   __restrict__ ci) {
    int idx = blockIdx.x * TPB + threadIdx.x;
    int i = idx >> 12;
    int j = idx & (NN - 1);
    float f = __ldg(&scal[__ldg(&ci[i]) * 2 + __ldg(&ci[j])]);
    g_weff[idx] = __fmul_rn(__ldg(&W[idx]), f);
}

// ------------------------------------------------------------------
// FF drive with order-preserving active-row compaction.
// CTA per (t,b); 256 threads x 16 columns.
// ------------------------------------------------------------------
__global__ void ff_kernel(const float* __restrict__ sp,
                          const float* __restrict__ wff,
                          const float* __restrict__ sff,
                          const int*   __restrict__ ciff,
                          const int*   __restrict__ ci) {
    __shared__ int    s_act[NI_];
    __shared__ float2 s_fv[NI_];
    __shared__ int    s_cnt[33];

    const int x   = blockIdx.x;
    const int t   = x >> 3;
    const int b   = x & 7;
    const int tid = threadIdx.x;
    const int lane = tid & 31;
    const int wrp  = tid >> 5;

    bool act[4]; int rnk[4];
#pragma unroll
    for (int r = 0; r < 4; ++r) {
        int i = r * TPB + tid;
        float sv = __ldg(&sp[((size_t)b * NT + t) * NI_ + i]);
        bool a = (sv != 0.0f);
        unsigned bal = __ballot_sync(0xffffffffu, a);
        if (lane == 0) s_cnt[r * 8 + wrp] = __popc(bal);
        act[r] = a;
        rnk[r] = __popc(bal & ((1u << lane) - 1u));
    }
    __syncthreads();
    if (tid == 0) {
        int run = 0;
#pragma unroll
        for (int s = 0; s < 32; ++s) { int c = s_cnt[s]; s_cnt[s] = run; run += c; }
        s_cnt[32] = run;
    }
    __syncthreads();
#pragma unroll
    for (int r = 0; r < 4; ++r) {
        if (act[r]) {
            int i = r * TPB + tid;
            int pos = s_cnt[r * 8 + wrp] + rnk[r];
            s_act[pos] = i << 12;
            int cf = __ldg(&ciff[i]) * 2;
            s_fv[pos] = make_float2(__ldg(&sff[cf]), __ldg(&sff[cf + 1]));
        }
    }
    __syncthreads();
    const int total = s_cnt[32];

    int ct16[16];
#pragma unroll
    for (int jj = 0; jj < 16; jj++) ct16[jj] = __ldg(&ci[jj * TPB + tid]);

    float acc[16];
#pragma unroll
    for (int jj = 0; jj < 16; jj++) acc[jj] = 0.0f;

    for (int k = 0; k < total; ++k) {
        int roff = s_act[k];
        float2 f = s_fv[k];
        const float* wr = wff + roff + tid;
#pragma unroll
        for (int jj = 0; jj < 16; jj++) {
            float w = __ldg(wr + jj * TPB);
            float fs = ct16[jj] ? f.y : f.x;
            acc[jj] = __fadd_rn(acc[jj], __fmul_rn(w, fs));
        }
    }
    size_t o = (size_t)x * NN + tid;
#pragma unroll
    for (int jj = 0; jj < 16; jj++) g_dff[o + jj * TPB] = acc[jj];
}

// ------------------------------------------------------------------
// Persistent sim: 256 CTAs x 256 threads. Threads 0-127 accumulate the
// EXC channel for 128 columns; threads 128-255 the INH channel for the
// same columns. Double-buffered tile-16 prefetch in the gather.
// ------------------------------------------------------------------
__global__ void __launch_bounds__(TPB)
sim_kernel(const int* __restrict__ ci, float* __restrict__ out, SimConsts C) {
    __shared__ int   s_lstE[4096];
    __shared__ int   s_lstI[4096];
    __shared__ float s_acc[128];
    __shared__ int   s_wsum[8];

    const int tid  = threadIdx.x;
    const int lane = tid & 31;
    const int wrp  = tid >> 5;
    const bool isE = (tid < 128);
    const int l128 = tid & 127;
    const int b    = blockIdx.x >> 5;
    const int jb   = (blockIdx.x & 31) << 7;
    const int j    = jb + l128;
    const int myct = __ldg(&ci[j]);

    const float dtt      = myct ? C.dtt1 : C.dtt0;
    const float refsteps = myct ? 10.0f : 20.0f;
    const float theta = -50.0f, u_reset = -65.0f, e_l = -70.0f, g_l = 10.0f;

    float v = e_l, ref = 0.0f;
    float h0 = 0, h1 = 0, h2 = 0, h3 = 0;
    float q0 = 0, q1 = 0, q2 = 0, q3 = 0;

    const float* __restrict__ Wcol = g_weff + j;
    float* outp = out + ((size_t)b * NT) * NN + j;
    const size_t dffbase = (size_t)b * NN + j;

    float dff_cur = 0.0f, dff_next = 0.0f;
    if (isE) dff_cur = __ldg(&g_dff[dffbase]);   // t = 0

    for (int t = 0; t < NT; ++t) {
        const int p = t & 1;

        // ---- 1. read masks, build per-type ascending compact lists ----
        unsigned mword = __ldcg(&g_mask[p][isE ? 0 : 1][b][l128]);
        int c = __popc(mword);
        int incl = c;
#pragma unroll
        for (int d = 1; d < 32; d <<= 1) {
            int nb2 = __shfl_up_sync(0xffffffffu, incl, d);
            if (lane >= d) incl += nb2;
        }
        if (lane == 31) s_wsum[wrp] = incl;
        __syncthreads();
        const int totE = s_wsum[0] + s_wsum[1] + s_wsum[2] + s_wsum[3];
        const int totI = s_wsum[4] + s_wsum[5] + s_wsum[6] + s_wsum[7];
        {
            int gbase = isE ? 0 : 4;
            int off = 0;
            for (int k = gbase; k < wrp; ++k) off += s_wsum[k];
            int base = off + incl - c;
            int* dst = isE ? s_lstE : s_lstI;
            unsigned m = mword;
            int ib = l128 << 5;
            while (m) {
                int bit = __ffs(m) - 1;
                m &= m - 1;
                dst[base++] = (ib + bit) << 12;
            }
        }
        __syncthreads();

        // prefetch next step's FF drive (independent of masks)
        if (isE && t + 1 < NT)
            dff_next = __ldg(&g_dff[(size_t)(t + 1) * (NB * NN) + dffbase]);

        // ---- 2. gather (double-buffered tiles of 16; padded adds are +0.0) ----
        const int  tot = isE ? totE : totI;
        const int* lst = isE ? s_lstE : s_lstI;
        float acc = 0.0f;
        {
            float bA[16], bB[16];
#pragma unroll
            for (int u = 0; u < 16; ++u)
                bA[u] = (u < tot) ? __ldg(Wcol + lst[u]) : 0.0f;
            for (int base = 0; base < tot; base += 32) {
#pragma unroll
                for (int u = 0; u < 16; ++u) {
                    int k = base + 16 + u;
                    bB[u] = (k < tot) ? __ldg(Wcol + lst[k]) : 0.0f;
                }
#pragma unroll
                for (int u = 0; u < 16; ++u) acc = __fadd_rn(acc, bA[u]);
#pragma unroll
                for (int u = 0; u < 16; ++u) {
                    int k = base + 32 + u;
                    bA[u] = (k < tot) ? __ldg(Wcol + lst[k]) : 0.0f;
                }
#pragma unroll
                for (int u = 0; u < 16; ++u) acc = __fadd_rn(acc, bB[u]);
            }
        }
        if (!isE) s_acc[l128] = acc;
        __syncthreads();

        // ---- 3. membrane update on E-threads (own the neuron state) ----
        if (isE) {
            float acc_e = acc;
            float acc_i = s_acc[l128];
            h0 = __fmaf_rn(h0, C.ar[0], acc_e);
            h1 = __fmaf_rn(h1, C.ar[1], __fmul_rn(acc_e, 0.5f));
            h2 = __fmaf_rn(h2, C.ar[2], acc_i);
            h3 = __fmaf_rn(h3, C.ar[3], dff_cur);
            q0 = __fmaf_rn(q0, C.ad[0], __fmul_rn(C.omad[0], h0));
            q1 = __fmaf_rn(q1, C.ad[1], __fmul_rn(C.omad[1], h1));
            q2 = __fmaf_rn(q2, C.ad[2], __fmul_rn(C.omad[2], h2));
            q3 = __fmaf_rn(q3, C.ad[3], __fmul_rn(C.omad[3], h3));

            float I = __fmul_rn(q0, __fsub_rn(C.esyn[0], v));
            I = __fadd_rn(I, __fmul_rn(q1, __fsub_rn(C.esyn[1], v)));
            I = __fadd_rn(I, __fmul_rn(q2, __fsub_rn(C.esyn[2], v)));
            I = __fadd_rn(I, __fmul_rn(q3, __fsub_rn(C.esyn[3], v)));

            float vn = __fmaf_rn(dtt,
                                 __fadd_rn(__fsub_rn(e_l, v), __fdiv_rn(I, g_l)),
                                 v);
            bool refr = (ref > 0.0f);
            if (refr) vn = u_reset;
            bool  spk = (!refr) && (vn > theta);
            float sn  = spk ? 1.0f : 0.0f;
            v   = spk ? u_reset : vn;
            ref = spk ? refsteps : fmaxf(__fsub_rn(ref, 1.0f), 0.0f);

            unsigned be = __ballot_sync(0xffffffffu, spk && (myct == 0));
            unsigned bi = __ballot_sync(0xffffffffu, spk && (myct == 1));
            if (lane == 0) {
                const int qb   = p ^ 1;
                const int word = (jb >> 5) + wrp;
                g_mask[qb][0][b][word] = be;
                g_mask[qb][1][b][word] = bi;
            }
            outp[(size_t)t * NN] = sn;
        }
        dff_cur = dff_next;

        // ---- 4. grid barrier ----
        if (t != NT - 1) {
            __threadfence();
            __syncthreads();
            if (tid == 0) {
                atomicAdd(&g_count, 1u);
                const unsigned target = (unsigned)NCTA * (unsigned)(t + 1);
                while (*(volatile unsigned*)&g_count < target) { }
            }
            __syncthreads();
        }
    }
}

// ------------------------------------------------------------------
extern "C" void kernel_launch(void* const* d_in, const int* in_sizes, int n_in,
                              void* d_out, int out_size) {
    const float* in_spikes = (const float*)d_in[0];
    const float* weights   = (const float*)d_in[1];
    const float* wff       = (const float*)d_in[2];
    const float* scal      = (const float*)d_in[3];
    const float* scalff    = (const float*)d_in[4];
    const int*   ci        = (const int*)  d_in[5];
    const int*   ciff      = (const int*)  d_in[6];
    float*       out       = (float*)d_out;

    const float tau_rise[4]  = {0.5f, 2.0f, 0.5f, 0.5f};
    const float tau_decay[4] = {2.0f, 100.0f, 5.0f, 2.0f};
    SimConsts C;
    for (int s = 0; s < 4; ++s) {
        float qr = -(0.1f / tau_rise[s]);
        float qd = -(0.1f / tau_decay[s]);
        C.ar[s]   = (float)exp((double)qr);
        C.ad[s]   = (float)exp((double)qd);
        C.omad[s] = 1.0f - C.ad[s];
    }
    C.esyn[0] = 0.0f; C.esyn[1] = 0.0f; C.esyn[2] = -80.0f; C.esyn[3] = 0.0f;
    C.dtt0 = 0.1f / 20.0f;
    C.dtt1 = 0.1f / 10.0f;

    init_kernel<<<8, TPB>>>();
    weff_kernel<<<(NN * NN) / TPB, TPB>>>(weights, scal, ci);
    ff_kernel<<<NT * NB, TPB>>>(in_spikes, wff, scalff, ciff, ci);
    sim_kernel<<<NCTA, TPB>>>(ci, out, C);
}

// round 3
// speedup vs baseline: 1.2276x; 1.1217x over previous
#include <cuda_runtime.h>
#include <math.h>

#define NN    4096
#define NI_   1024
#define NB    8
#define NT    500
#define NWORD 128          // NN/32
#define SIM_CTAS 128       // 8 batches x 16 col-blocks (256 cols each)
#define SIM_TPB  128       // 64 E threads + 64 I threads, 4 cols/thread

// ---- device scratch ----
__device__ float     g_weff[(size_t)NN * NN];          // 64 MB
__device__ float     g_dff[(size_t)NT * NB * NN];      // 65.5 MB [t][b*N+j]
__device__ unsigned  g_mask[2][2][NB][NWORD];          // [buf][type][batch][word]
__device__ unsigned  g_count;

struct SimConsts {
    float ar[4], ad[4], omad[4], esyn[4];
    float dtt0, dtt1;
};

// ------------------------------------------------------------------
__global__ void init_kernel() {
    int idx = blockIdx.x * blockDim.x + threadIdx.x;
    if (idx == 0) g_count = 0u;
    if (idx < 2 * NB * NWORD) ((unsigned*)g_mask[0])[idx] = 0u;
}

// ------------------------------------------------------------------
__global__ void weff_kernel(const float* __restrict__ W,
                            const float* __restrict__ scal,
                            const int*   __restrict__ ci) {
    int idx = blockIdx.x * 256 + threadIdx.x;          // float4 index
    int e = idx << 2;
    int i = e >> 12;
    int j = e & (NN - 1);
    float4 w = __ldg((const float4*)W + idx);
    int cri = __ldg(&ci[i]) * 2;
    float4 r;
    r.x = __fmul_rn(w.x, __ldg(&scal[cri + __ldg(&ci[j + 0])]));
    r.y = __fmul_rn(w.y, __ldg(&scal[cri + __ldg(&ci[j + 1])]));
    r.z = __fmul_rn(w.z, __ldg(&scal[cri + __ldg(&ci[j + 2])]));
    r.w = __fmul_rn(w.w, __ldg(&scal[cri + __ldg(&ci[j + 3])]));
    ((float4*)g_weff)[idx] = r;
}

// ------------------------------------------------------------------
// FF drive with order-preserving active-row compaction (unchanged from R2).
// ------------------------------------------------------------------
__global__ void ff_kernel(const float* __restrict__ sp,
                          const float* __restrict__ wff,
                          const float* __restrict__ sff,
                          const int*   __restrict__ ciff,
                          const int*   __restrict__ ci) {
    __shared__ int    s_act[NI_];
    __shared__ float2 s_fv[NI_];
    __shared__ int    s_cnt[33];

    const int x   = blockIdx.x;
    const int t   = x >> 3;
    const int b   = x & 7;
    const int tid = threadIdx.x;
    const int lane = tid & 31;
    const int wrp  = tid >> 5;

    bool act[4]; int rnk[4];
#pragma unroll
    for (int r = 0; r < 4; ++r) {
        int i = r * 256 + tid;
        float sv = __ldg(&sp[((size_t)b * NT + t) * NI_ + i]);
        bool a = (sv != 0.0f);
        unsigned bal = __ballot_sync(0xffffffffu, a);
        if (lane == 0) s_cnt[r * 8 + wrp] = __popc(bal);
        act[r] = a;
        rnk[r] = __popc(bal & ((1u << lane) - 1u));
    }
    __syncthreads();
    if (tid == 0) {
        int run = 0;
#pragma unroll
        for (int s = 0; s < 32; ++s) { int c = s_cnt[s]; s_cnt[s] = run; run += c; }
        s_cnt[32] = run;
    }
    __syncthreads();
#pragma unroll
    for (int r = 0; r < 4; ++r) {
        if (act[r]) {
            int i = r * 256 + tid;
            int pos = s_cnt[r * 8 + wrp] + rnk[r];
            s_act[pos] = i << 12;
            int cf = __ldg(&ciff[i]) * 2;
            s_fv[pos] = make_float2(__ldg(&sff[cf]), __ldg(&sff[cf + 1]));
        }
    }
    __syncthreads();
    const int total = s_cnt[32];

    int ct16[16];
#pragma unroll
    for (int jj = 0; jj < 16; jj++) ct16[jj] = __ldg(&ci[jj * 256 + tid]);

    float acc[16];
#pragma unroll
    for (int jj = 0; jj < 16; jj++) acc[jj] = 0.0f;

    for (int k = 0; k < total; ++k) {
        int roff = s_act[k];
        float2 f = s_fv[k];
        const float* wr = wff + roff + tid;
#pragma unroll
        for (int jj = 0; jj < 16; jj++) {
            float w = __ldg(wr + jj * 256);
            float fs = ct16[jj] ? f.y : f.x;
            acc[jj] = __fadd_rn(acc[jj], __fmul_rn(w, fs));
        }
    }
    size_t o = (size_t)x * NN + tid;
#pragma unroll
    for (int jj = 0; jj < 16; jj++) g_dff[o + jj * 256] = acc[jj];
}

// ------------------------------------------------------------------
// Persistent sim: 128 CTAs (1/SM) x 128 threads.
// Threads 0-63: EXC channel for 4 columns each (256 cols per CTA).
// Threads 64-127: INH channel for the same columns.
// float4 gather; CG-style release/acquire grid barrier (no L1 flush).
// ------------------------------------------------------------------
__global__ void __launch_bounds__(SIM_TPB, 1)
sim_kernel(const int* __restrict__ ci, float* __restrict__ out, SimConsts C) {
    __shared__ int           s_lstE[NN];
    __shared__ int           s_lstI[NN];
    __shared__ float         s_accI[256];
    __shared__ int           s_wsum[4];
    __shared__ unsigned char s_nibE[64];
    __shared__ unsigned char s_nibI[64];

    const int tid  = threadIdx.x;
    const int lane = tid & 31;
    const int wrp  = tid >> 5;
    const bool isE = (wrp < 2);
    const int q    = isE ? tid : (tid - 64);       // quad 0..63
    const int b    = blockIdx.x >> 4;
    const int jb   = (blockIdx.x & 15) << 8;
    const int j0   = jb + (q << 2);

    const int type = wrp >> 1;                     // list this warp builds
    const int half = wrp & 1;

    int ct[4]; float dtt[4], refst[4];
#pragma unroll
    for (int k = 0; k < 4; ++k) {
        ct[k]    = __ldg(&ci[j0 + k]);
        dtt[k]   = ct[k] ? C.dtt1 : C.dtt0;
        refst[k] = ct[k] ? 10.0f : 20.0f;
    }
    const float theta = -50.0f, u_reset = -65.0f, e_l = -70.0f, g_l = 10.0f;

    float v[4], ref[4], h0[4], h1[4], h2[4], h3[4], q0[4], q1[4], q2[4], q3[4];
#pragma unroll
    for (int k = 0; k < 4; ++k) {
        v[k] = e_l; ref[k] = 0.0f;
        h0[k] = h1[k] = h2[k] = h3[k] = 0.0f;
        q0[k] = q1[k] = q2[k] = q3[k] = 0.0f;
    }

    const float4* __restrict__ Wq = ((const float4*)g_weff) + (j0 >> 2);
    float* outp = out + ((size_t)b * NT) * NN + j0;
    const float* dffp = g_dff + (size_t)b * NN + j0;

    float4 dff_cur = make_float4(0, 0, 0, 0), dff_next = dff_cur;
    if (isE) dff_cur = __ldg((const float4*)dffp);

    for (int t = 0; t < NT; ++t) {
        const int p = t & 1;

        // ---- 1. masks -> ascending compact lists (per type) ----
        unsigned w0 = __ldcg(&g_mask[p][type][b][half * 64 + lane]);
        unsigned w1 = __ldcg(&g_mask[p][type][b][half * 64 + 32 + lane]);
        int c0 = __popc(w0), c1 = __popc(w1);
        int s0 = c0, s1 = c1;
#pragma unroll
        for (int d = 1; d < 32; d <<= 1) {
            int t0 = __shfl_up_sync(0xffffffffu, s0, d);
            int t1 = __shfl_up_sync(0xffffffffu, s1, d);
            if (lane >= d) { s0 += t0; s1 += t1; }
        }
        int tot0    = __shfl_sync(0xffffffffu, s0, 31);
        int tothalf = tot0 + __shfl_sync(0xffffffffu, s1, 31);
        if (lane == 31) s_wsum[wrp] = tothalf;
        __syncthreads();
        const int totE = s_wsum[0] + s_wsum[1];
        const int totI = s_wsum[2] + s_wsum[3];
        {
            int base_half = half ? s_wsum[type * 2] : 0;
            int* dst = type ? s_lstI : s_lstE;
            int pos = base_half + s0 - c0;
            int ib  = (half * 64 + lane) << 5;
            unsigned m = w0;
            while (m) {
                int bit = __ffs(m) - 1; m &= m - 1;
                dst[pos++] = (ib + bit) << 10;          // i * 1024 (float4 stride)
            }
            pos = base_half + tot0 + s1 - c1;
            ib  = (half * 64 + 32 + lane) << 5;
            m = w1;
            while (m) {
                int bit = __ffs(m) - 1; m &= m - 1;
                dst[pos++] = (ib + bit) << 10;
            }
        }
        __syncthreads();

        if (isE && t + 1 < NT)
            dff_next = __ldg((const float4*)(dffp + (size_t)(t + 1) * (NB * NN)));

        // ---- 2. float4 gather, double-buffered tiles of 8 ----
        const int  tot = isE ? totE : totI;
        const int* lst = isE ? s_lstE : s_lstI;
        const float4 Z4 = make_float4(0, 0, 0, 0);
        float a0 = 0.0f, a1 = 0.0f, a2 = 0.0f, a3 = 0.0f;
        {
            float4 bA[8], bB[8];
#pragma unroll
            for (int u = 0; u < 8; ++u)
                bA[u] = (u < tot) ? __ldg(Wq + lst[u]) : Z4;
            for (int base = 0; base < tot; base += 16) {
#pragma unroll
                for (int u = 0; u < 8; ++u) {
                    int k = base + 8 + u;
                    bB[u] = (k < tot) ? __ldg(Wq + lst[k]) : Z4;
                }
#pragma unroll
                for (int u = 0; u < 8; ++u) {
                    a0 = __fadd_rn(a0, bA[u].x);
                    a1 = __fadd_rn(a1, bA[u].y);
                    a2 = __fadd_rn(a2, bA[u].z);
                    a3 = __fadd_rn(a3, bA[u].w);
                }
#pragma unroll
                for (int u = 0; u < 8; ++u) {
                    int k = base + 16 + u;
                    bA[u] = (k < tot) ? __ldg(Wq + lst[k]) : Z4;
                }
#pragma unroll
                for (int u = 0; u < 8; ++u) {
                    a0 = __fadd_rn(a0, bB[u].x);
                    a1 = __fadd_rn(a1, bB[u].y);
                    a2 = __fadd_rn(a2, bB[u].z);
                    a3 = __fadd_rn(a3, bB[u].w);
                }
            }
        }
        if (!isE) {
            s_accI[q * 4 + 0] = a0; s_accI[q * 4 + 1] = a1;
            s_accI[q * 4 + 2] = a2; s_accI[q * 4 + 3] = a3;
        }
        __syncthreads();

        // ---- 3. membrane update (E threads own state for 4 neurons) ----
        if (isE) {
            float acc_e[4] = {a0, a1, a2, a3};
            float dffv[4]  = {dff_cur.x, dff_cur.y, dff_cur.z, dff_cur.w};
            float sn[4];
            unsigned nibE = 0, nibI = 0;
#pragma unroll
            for (int k = 0; k < 4; ++k) {
                float acc_i = s_accI[q * 4 + k];
                h0[k] = __fmaf_rn(h0[k], C.ar[0], acc_e[k]);
                h1[k] = __fmaf_rn(h1[k], C.ar[1], __fmul_rn(acc_e[k], 0.5f));
                h2[k] = __fmaf_rn(h2[k], C.ar[2], acc_i);
                h3[k] = __fmaf_rn(h3[k], C.ar[3], dffv[k]);
                q0[k] = __fmaf_rn(q0[k], C.ad[0], __fmul_rn(C.omad[0], h0[k]));
                q1[k] = __fmaf_rn(q1[k], C.ad[1], __fmul_rn(C.omad[1], h1[k]));
                q2[k] = __fmaf_rn(q2[k], C.ad[2], __fmul_rn(C.omad[2], h2[k]));
                q3[k] = __fmaf_rn(q3[k], C.ad[3], __fmul_rn(C.omad[3], h3[k]));

                float I = __fmul_rn(q0[k], __fsub_rn(C.esyn[0], v[k]));
                I = __fadd_rn(I, __fmul_rn(q1[k], __fsub_rn(C.esyn[1], v[k])));
                I = __fadd_rn(I, __fmul_rn(q2[k], __fsub_rn(C.esyn[2], v[k])));
                I = __fadd_rn(I, __fmul_rn(q3[k], __fsub_rn(C.esyn[3], v[k])));

                float vn = __fmaf_rn(dtt[k],
                                     __fadd_rn(__fsub_rn(e_l, v[k]),
                                               __fdiv_rn(I, g_l)),
                                     v[k]);
                bool refr = (ref[k] > 0.0f);
                if (refr) vn = u_reset;
                bool spk = (!refr) && (vn > theta);
                sn[k]  = spk ? 1.0f : 0.0f;
                v[k]   = spk ? u_reset : vn;
                ref[k] = spk ? refst[k] : fmaxf(__fsub_rn(ref[k], 1.0f), 0.0f);
                unsigned bit = spk ? (1u << k) : 0u;
                if (ct[k] == 0) nibE |= bit; else nibI |= bit;
            }
            s_nibE[q] = (unsigned char)nibE;
            s_nibI[q] = (unsigned char)nibI;
            *(float4*)(outp + (size_t)t * NN) = make_float4(sn[0], sn[1], sn[2], sn[3]);
        }
        dff_cur = dff_next;
        __syncthreads();

        // ---- 4. assemble + publish mask words for step t+1 ----
        if (tid < 8) {
            unsigned we = 0, wi = 0;
#pragma unroll
            for (int k = 0; k < 8; ++k) {
                we |= ((unsigned)s_nibE[tid * 8 + k]) << (4 * k);
                wi |= ((unsigned)s_nibI[tid * 8 + k]) << (4 * k);
            }
            const int qb = p ^ 1;
            const int word = (jb >> 5) + tid;
            g_mask[qb][0][b][word] = we;
            g_mask[qb][1][b][word] = wi;
        }

        // ---- 5. grid barrier: red.release + ld.acquire (no L1 flush) ----
        if (t != NT - 1) {
            __syncthreads();
            if (tid == 0) {
                asm volatile("red.release.gpu.global.add.u32 [%0], %1;"
                             :: "l"(&g_count), "r"(1u) : "memory");
                const unsigned target = (unsigned)SIM_CTAS * (unsigned)(t + 1);
                unsigned cv;
                do {
                    asm volatile("ld.acquire.gpu.global.u32 %0, [%1];"
                                 : "=r"(cv) : "l"(&g_count));
                } while (cv < target);
            }
            __syncthreads();
        }
    }
}

// ------------------------------------------------------------------
extern "C" void kernel_launch(void* const* d_in, const int* in_sizes, int n_in,
                              void* d_out, int out_size) {
    const float* in_spikes = (const float*)d_in[0];
    const float* weights   = (const float*)d_in[1];
    const float* wff       = (const float*)d_in[2];
    const float* scal      = (const float*)d_in[3];
    const float* scalff    = (const float*)d_in[4];
    const int*   ci        = (const int*)  d_in[5];
    const int*   ciff      = (const int*)  d_in[6];
    float*       out       = (float*)d_out;

    const float tau_rise[4]  = {0.5f, 2.0f, 0.5f, 0.5f};
    const float tau_decay[4] = {2.0f, 100.0f, 5.0f, 2.0f};
    SimConsts C;
    for (int s = 0; s < 4; ++s) {
        float qr = -(0.1f / tau_rise[s]);
        float qd = -(0.1f / tau_decay[s]);
        C.ar[s]   = (float)exp((double)qr);
        C.ad[s]   = (float)exp((double)qd);
        C.omad[s] = 1.0f - C.ad[s];
    }
    C.esyn[0] = 0.0f; C.esyn[1] = 0.0f; C.esyn[2] = -80.0f; C.esyn[3] = 0.0f;
    C.dtt0 = 0.1f / 20.0f;
    C.dtt1 = 0.1f / 10.0f;

    init_kernel<<<8, 256>>>();
    weff_kernel<<<(NN * NN / 4) / 256, 256>>>(weights, scal, ci);
    ff_kernel<<<NT * NB, 256>>>(in_spikes, wff, scalff, ciff, ci);
    sim_kernel<<<SIM_CTAS, SIM_TPB>>>(ci, out, C);
}